// round 14
// baseline (speedup 1.0000x reference)
#include <cuda_runtime.h>
#include <math.h>
#include <stdint.h>

#define NN 40000
#define EE 640000
#define ET 680000   // edges + self loops
#define CAP 128     // padded CSR capacity per node (max observed degree ~35)

// ---------------- scratch (device globals; no allocation) ----------------
__device__ float g_h[NN * 256];      // post-GEMM features of current layer
__device__ float g_x1[NN * 256];
__device__ float g_x2[NN * 128];
__device__ float g_comb[NN * 256];   // [x3 | pos_features]
__device__ float g_p1[NN * 64];
__device__ float g_p2[NN * 128];
__device__ float g_es[NN * 4];
__device__ float g_ed[NN * 4];
__device__ int   g_cnt[NN];
__device__ int   g_srcs[(size_t)NN * CAP];
__device__ uint32_t g_wt[122880];    // pre-converted+swizzled tf32 weights

// weight offsets in g_wt
#define OFF_W1  0        // 256x64
#define OFF_W2  16384    // 128x256
#define OFF_W3  49152    // 128x128
#define OFF_PW2 65536    // 128x64
#define OFF_PW3 73728    // 128x128
#define OFF_FW  90112    // 128x256
#define WT_TOTAL 122880

// ---------------- tf32 helpers ----------------
__device__ __forceinline__ uint32_t f2tf32(float f) {
    uint32_t u;
    asm("cvt.rna.tf32.f32 %0, %1;" : "=r"(u) : "f"(f));
    return u;
}

__device__ __forceinline__ void mma_tf32(float& c0, float& c1, float& c2, float& c3,
                                         uint32_t a0, uint32_t a1, uint32_t a2, uint32_t a3,
                                         uint32_t b0, uint32_t b1) {
    asm volatile(
        "mma.sync.aligned.m16n8k8.row.col.f32.tf32.tf32.f32 "
        "{%0,%1,%2,%3}, {%4,%5,%6,%7}, {%8,%9}, {%0,%1,%2,%3};\n"
        : "+f"(c0), "+f"(c1), "+f"(c2), "+f"(c3)
        : "r"(a0), "r"(a1), "r"(a2), "r"(a3), "r"(b0), "r"(b1));
}

// k-pair interleaved physical column: (k, k+4) become adjacent words
__device__ __forceinline__ int kphys(int kk) {
    return ((kk >> 3) << 3) | ((kk & 3) << 1) | ((kk >> 2) & 1);
}

// ---------------- weight prep: fp32 [m][k] -> tf32, k-pair swizzled --------
__global__ void wprep(const float* __restrict__ W1, const float* __restrict__ W2,
                      const float* __restrict__ W3, const float* __restrict__ pw2,
                      const float* __restrict__ pw3, const float* __restrict__ fw) {
    int i = blockIdx.x * blockDim.x + threadIdx.x;
    const float* src; int off, kdim, li;
    if (i < 16384)       { src = W1;  off = OFF_W1;  kdim = 64;  li = i; }
    else if (i < 49152)  { src = W2;  off = OFF_W2;  kdim = 256; li = i - 16384; }
    else if (i < 65536)  { src = W3;  off = OFF_W3;  kdim = 128; li = i - 49152; }
    else if (i < 73728)  { src = pw2; off = OFF_PW2; kdim = 64;  li = i - 65536; }
    else if (i < 90112)  { src = pw3; off = OFF_PW3; kdim = 128; li = i - 73728; }
    else if (i < WT_TOTAL) { src = fw; off = OFF_FW; kdim = 256; li = i - 90112; }
    else return;
    int r = li / kdim;
    int kl = li - r * kdim;
    g_wt[off + r * kdim + (kl & ~15) + kphys(kl & 15)] = f2tf32(src[li]);
}

// ---------------- GEMM (tf32 tensor core): C[n,m] = A[n,k] @ Bt[m,k]^T -----
// 64x64 CTA tile, 128 threads / 4 warps, warp = 16 rows x 64 cols.
// Bt = pre-converted tf32, k-pair swizzled. n%64==0, m%64==0, k%16==0.
#define SMS 20   // smem row stride (words)
__global__ void __launch_bounds__(128)
gemm_nt(const float* __restrict__ A, const uint32_t* __restrict__ Bt,
        const float* __restrict__ bias,
        const float* __restrict__ bng, const float* __restrict__ bnb,
        float* __restrict__ C, int ldc,
        float* __restrict__ C2, int ldc2,
        int n, int m, int k,
        const float* __restrict__ a_sf, const float* __restrict__ a_df,
        float* __restrict__ es, float* __restrict__ ed, int H, int headC) {
    __shared__ uint32_t As[2][64][SMS];
    __shared__ uint32_t Bs[2][64][SMS];
    const int tid = threadIdx.x;
    const int rowBase = blockIdx.y * 64;
    const int colBase = blockIdx.x * 64;
    const int lr = tid >> 2;           // 0..31 (+32)
    const int lc = (tid & 3) * 4;      // 0,4,8,12
    const int warp = tid >> 5;
    const int lane = tid & 31;
    const int g = lane >> 2;
    const int tg = lane & 3;
    const int wrow = warp * 16;

    float c[8][4];
    #pragma unroll
    for (int t = 0; t < 8; t++)
        #pragma unroll
        for (int q = 0; q < 4; q++) c[t][q] = 0.f;

    float4 av[2];
    uint4 bw[2];
    #pragma unroll
    for (int h = 0; h < 2; h++) {
        av[h] = *(const float4*)(A + (size_t)(rowBase + lr + h * 32) * k + lc);
        bw[h] = *(const uint4*)(Bt + (size_t)(colBase + lr + h * 32) * k + lc);
    }
    #pragma unroll
    for (int h = 0; h < 2; h++) {
        int rr = lr + h * 32;
        As[0][rr][kphys(lc + 0)] = f2tf32(av[h].x); As[0][rr][kphys(lc + 1)] = f2tf32(av[h].y);
        As[0][rr][kphys(lc + 2)] = f2tf32(av[h].z); As[0][rr][kphys(lc + 3)] = f2tf32(av[h].w);
        *(uint4*)&Bs[0][rr][lc] = bw[h];
    }
    __syncthreads();

    int st = 0;
    const int T = k / 16;
    for (int it = 0; it < T; it++) {
        bool hasNext = (it + 1) < T;
        if (hasNext) {
            int k0 = (it + 1) * 16;
            #pragma unroll
            for (int h = 0; h < 2; h++) {
                av[h] = *(const float4*)(A + (size_t)(rowBase + lr + h * 32) * k + k0 + lc);
                bw[h] = *(const uint4*)(Bt + (size_t)(colBase + lr + h * 32) * k + k0 + lc);
            }
        }
        #pragma unroll
        for (int kc = 0; kc < 16; kc += 8) {
            const int kb = kc + 2 * tg;
            uint2 aP0 = *(const uint2*)&As[st][wrow + g][kb];
            uint2 aP1 = *(const uint2*)&As[st][wrow + g + 8][kb];
            #pragma unroll
            for (int t = 0; t < 8; t++) {
                uint2 bP = *(const uint2*)&Bs[st][t * 8 + g][kb];
                mma_tf32(c[t][0], c[t][1], c[t][2], c[t][3],
                         aP0.x, aP1.x, aP0.y, aP1.y, bP.x, bP.y);
            }
        }
        if (hasNext) {
            int ns = st ^ 1;
            #pragma unroll
            for (int h = 0; h < 2; h++) {
                int rr = lr + h * 32;
                As[ns][rr][kphys(lc + 0)] = f2tf32(av[h].x); As[ns][rr][kphys(lc + 1)] = f2tf32(av[h].y);
                As[ns][rr][kphys(lc + 2)] = f2tf32(av[h].z); As[ns][rr][kphys(lc + 3)] = f2tf32(av[h].w);
                *(uint4*)&Bs[ns][rr][lc] = bw[h];
            }
            __syncthreads();
            st = ns;
        }
    }

    // main store epilogue: rows wrow+g(+8), cols t*8+2tg(+1)
    const float inv = rsqrtf(1.f + 1e-5f);
    #pragma unroll
    for (int rr = 0; rr < 2; rr++) {
        int r = rowBase + wrow + g + rr * 8;
        #pragma unroll
        for (int t = 0; t < 8; t++) {
            int c0i = colBase + t * 8 + 2 * tg;
            float v0 = c[t][rr * 2 + 0];
            float v1 = c[t][rr * 2 + 1];
            if (bias) { v0 += bias[c0i]; v1 += bias[c0i + 1]; }
            if (bng) {
                v0 = v0 * (bng[c0i] * inv) + bnb[c0i];
                v1 = v1 * (bng[c0i + 1] * inv) + bnb[c0i + 1];
                v0 = v0 > 0.f ? v0 : 0.f;
                v1 = v1 > 0.f ? v1 : 0.f;
            }
            float2 o2 = make_float2(v0, v1);
            *(float2*)(C + (size_t)r * ldc + c0i) = o2;
            if (C2) *(float2*)(C2 + (size_t)r * ldc2 + c0i) = o2;
        }
    }

    // fused attention scores (raw accumulator dotted with a_s / a_d)
    if (es) {
        #pragma unroll
        for (int rr = 0; rr < 2; rr++) {
            float sv = 0.f, dv = 0.f;
            #pragma unroll
            for (int t = 0; t < 8; t++) {
                int c0i = colBase + t * 8 + 2 * tg;
                sv += c[t][rr * 2] * a_sf[c0i] + c[t][rr * 2 + 1] * a_sf[c0i + 1];
                dv += c[t][rr * 2] * a_df[c0i] + c[t][rr * 2 + 1] * a_df[c0i + 1];
            }
            #pragma unroll
            for (int o = 1; o < 4; o <<= 1) {
                sv += __shfl_xor_sync(0xffffffffu, sv, o);
                dv += __shfl_xor_sync(0xffffffffu, dv, o);
            }
            if (tg == 0) {
                int r = rowBase + wrow + g + rr * 8;
                if (headC == 64) {
                    int h0 = colBase >> 6;
                    es[r * H + h0] = sv;
                    ed[r * H + h0] = dv;
                } else {
                    // headC == 128: each 64-col block writes its own partial slot
                    int slot = colBase >> 6;   // 0 or 1
                    es[r * 2 + slot] = sv;
                    ed[r * 2 + slot] = dv;
                }
            }
        }
    }
}

// ---------------- padded CSR build ----------------
__global__ void scatter_kernel(const int* __restrict__ ei) {
    int e = blockIdx.x * blockDim.x + threadIdx.x;
    if (e >= ET) return;
    int sN, d;
    if (e < EE) { sN = ei[e]; d = ei[EE + e]; } else { sN = d = e - EE; }
    int pos = atomicAdd(&g_cnt[d], 1);
    if (pos < CAP) g_srcs[(size_t)d * CAP + pos] = sN;
}

// ---------------- GAT aggregate + softmax + epilogue ----------------------
// SPLIT=1 (layer 3): scores are two partials es[2r]+es[2r+1].
template<int H, int F, int MODE, int WPN, int SPLIT>
__global__ void gat_agg(const float* __restrict__ bias,
                        const float* __restrict__ lng, const float* __restrict__ lnb,
                        float* __restrict__ out, float* __restrict__ out2) {
    constexpr int HW = H / WPN;
    constexpr int C = F / H;
    constexpr int NPB = 8 / WPN;
    __shared__ float ssum[8], ssum2[8];

    const int lane = threadIdx.x & 31;
    const int warp = threadIdx.x >> 5;
    const int node = blockIdx.x * NPB + warp / WPN;
    const int half = warp % WPN;
    const int colOff = half * 128;
    const int hbase = colOff / C;
    const int hl = (4 * lane) / C;

    const int cnt = min(g_cnt[node], CAP);
    float edn[HW];
    if (SPLIT) {
        edn[0] = g_ed[node * 2] + g_ed[node * 2 + 1];
    } else {
        #pragma unroll
        for (int h = 0; h < HW; h++) edn[h] = g_ed[node * H + hbase + h];
    }

    float4 acc0 = make_float4(0.f, 0.f, 0.f, 0.f);
    float4 acc1 = make_float4(0.f, 0.f, 0.f, 0.f);
    float dl[HW];
    #pragma unroll
    for (int h = 0; h < HW; h++) dl[h] = 0.f;

    const int* __restrict__ srcs = g_srcs + (size_t)node * CAP;

    for (int base = 0; base < cnt; base += 32) {
        int j = base + lane;
        int sj = 0;
        float w[HW];
        #pragma unroll
        for (int h = 0; h < HW; h++) w[h] = 0.f;
        if (j < cnt) {
            sj = srcs[j];
            #pragma unroll
            for (int h = 0; h < HW; h++) {
                float esv = SPLIT ? (g_es[sj * 2] + g_es[sj * 2 + 1])
                                  : g_es[sj * H + hbase + h];
                float v = esv + edn[h];
                v = v > 0.f ? v : 0.2f * v;
                w[h] = expf(v);
                dl[h] += w[h];
            }
        }
        int lim = min(32, cnt - base);
        int jj = 0;
        #pragma unroll 2
        for (; jj + 1 < lim; jj += 2) {
            int sb0 = __shfl_sync(0xffffffffu, sj, jj);
            int sb1 = __shfl_sync(0xffffffffu, sj, jj + 1);
            float ww0, ww1;
            {
                float wb0[HW], wb1[HW];
                #pragma unroll
                for (int h = 0; h < HW; h++) {
                    wb0[h] = __shfl_sync(0xffffffffu, w[h], jj);
                    wb1[h] = __shfl_sync(0xffffffffu, w[h], jj + 1);
                }
                ww0 = wb0[0]; ww1 = wb1[0];
                #pragma unroll
                for (int h = 1; h < HW; h++) {
                    if (hl == h) { ww0 = wb0[h]; ww1 = wb1[h]; }
                }
            }
            float4 hv0 = *(const float4*)(g_h + (size_t)sb0 * F + colOff + 4 * lane);
            float4 hv1 = *(const float4*)(g_h + (size_t)sb1 * F + colOff + 4 * lane);
            acc0.x += ww0 * hv0.x; acc0.y += ww0 * hv0.y;
            acc0.z += ww0 * hv0.z; acc0.w += ww0 * hv0.w;
            acc1.x += ww1 * hv1.x; acc1.y += ww1 * hv1.y;
            acc1.z += ww1 * hv1.z; acc1.w += ww1 * hv1.w;
        }
        if (jj < lim) {
            int sb0 = __shfl_sync(0xffffffffu, sj, jj);
            float wb0[HW];
            #pragma unroll
            for (int h = 0; h < HW; h++) wb0[h] = __shfl_sync(0xffffffffu, w[h], jj);
            float ww0 = wb0[0];
            #pragma unroll
            for (int h = 1; h < HW; h++) if (hl == h) ww0 = wb0[h];
            float4 hv0 = *(const float4*)(g_h + (size_t)sb0 * F + colOff + 4 * lane);
            acc0.x += ww0 * hv0.x; acc0.y += ww0 * hv0.y;
            acc0.z += ww0 * hv0.z; acc0.w += ww0 * hv0.w;
        }
    }
    acc0.x += acc1.x; acc0.y += acc1.y; acc0.z += acc1.z; acc0.w += acc1.w;

    #pragma unroll
    for (int h = 0; h < HW; h++) {
        #pragma unroll
        for (int o = 16; o > 0; o >>= 1)
            dl[h] += __shfl_xor_sync(0xffffffffu, dl[h], o);
    }

    float dsel = dl[0];
    #pragma unroll
    for (int h = 1; h < HW; h++) if (hl == h) dsel = dl[h];
    float dinv = 1.f / (dsel + 1e-16f);
    const int col = colOff + 4 * lane;
    float4 b4 = *(const float4*)(bias + col);
    float res[4];
    res[0] = acc0.x * dinv + b4.x;
    res[1] = acc0.y * dinv + b4.y;
    res[2] = acc0.z * dinv + b4.z;
    res[3] = acc0.w * dinv + b4.w;

    if (MODE == 0) {
        float s = 0.f, s2 = 0.f;
        #pragma unroll
        for (int q = 0; q < 4; q++) { s += res[q]; s2 += res[q] * res[q]; }
        #pragma unroll
        for (int o = 16; o > 0; o >>= 1) {
            s  += __shfl_xor_sync(0xffffffffu, s, o);
            s2 += __shfl_xor_sync(0xffffffffu, s2, o);
        }
        if (WPN == 2) {
            if (lane == 0) { ssum[warp] = s; ssum2[warp] = s2; }
            __syncthreads();
            s += ssum[warp ^ 1];
            s2 += ssum2[warp ^ 1];
        }
        float mu = s / F;
        float var = s2 / F - mu * mu;
        float rstd = rsqrtf(var + 1e-5f);
        float4 g4 = *(const float4*)(lng + col);
        float4 bb4 = *(const float4*)(lnb + col);
        float4 o4;
        o4.x = (res[0] - mu) * rstd * g4.x + bb4.x;
        o4.y = (res[1] - mu) * rstd * g4.y + bb4.y;
        o4.z = (res[2] - mu) * rstd * g4.z + bb4.z;
        o4.w = (res[3] - mu) * rstd * g4.w + bb4.w;
        o4.x = o4.x > 0.f ? o4.x : 0.f;
        o4.y = o4.y > 0.f ? o4.y : 0.f;
        o4.z = o4.z > 0.f ? o4.z : 0.f;
        o4.w = o4.w > 0.f ? o4.w : 0.f;
        *(float4*)(out + (size_t)node * F + col) = o4;
    } else {
        float4 o4 = make_float4(res[0], res[1], res[2], res[3]);
        *(float4*)(out + (size_t)node * F + col) = o4;
        *(float4*)(out2 + (size_t)node * 256 + col) = o4;
    }
}

// ---------------- pointnet layer 1: pos[N,3] -> p1[N,64] with BN+ReLU ------
__global__ void pn1_kernel(const float* __restrict__ pos,
                           const float* __restrict__ pw1, const float* __restrict__ pb1,
                           const float* __restrict__ bn1g, const float* __restrict__ bn1b,
                           float* __restrict__ p1) {
    int i = blockIdx.x * blockDim.x + threadIdx.x;
    if (i >= NN * 64) return;
    int node = i >> 6, c = i & 63;
    float px = pos[node * 3 + 0], py = pos[node * 3 + 1], pz = pos[node * 3 + 2];
    float s = pb1[c] + pw1[c * 3 + 0] * px + pw1[c * 3 + 1] * py + pw1[c * 3 + 2] * pz;
    const float inv = rsqrtf(1.f + 1e-5f);
    s = s * (bn1g[c] * inv) + bn1b[c];
    p1[i] = s > 0.f ? s : 0.f;
}

// ---------------- host ----------------
extern "C" void kernel_launch(void* const* d_in, const int* in_sizes, int n_in,
                              void* d_out, int out_size) {
    const float* x    = (const float*)d_in[0];
    const int*   ei   = (const int*)d_in[1];
    const float* pos  = (const float*)d_in[2];
    const float* W1   = (const float*)d_in[3];
    const float* a_s1 = (const float*)d_in[4];
    const float* a_d1 = (const float*)d_in[5];
    const float* bg1  = (const float*)d_in[6];
    const float* ln1g = (const float*)d_in[7];
    const float* ln1b = (const float*)d_in[8];
    const float* W2   = (const float*)d_in[9];
    const float* a_s2 = (const float*)d_in[10];
    const float* a_d2 = (const float*)d_in[11];
    const float* bg2  = (const float*)d_in[12];
    const float* ln2g = (const float*)d_in[13];
    const float* ln2b = (const float*)d_in[14];
    const float* W3   = (const float*)d_in[15];
    const float* a_s3 = (const float*)d_in[16];
    const float* a_d3 = (const float*)d_in[17];
    const float* bg3  = (const float*)d_in[18];
    const float* pw1  = (const float*)d_in[19];
    const float* pb1  = (const float*)d_in[20];
    const float* bn1g = (const float*)d_in[21];
    const float* bn1b = (const float*)d_in[22];
    const float* pw2  = (const float*)d_in[23];
    const float* pb2  = (const float*)d_in[24];
    const float* bn2g = (const float*)d_in[25];
    const float* bn2b = (const float*)d_in[26];
    const float* pw3  = (const float*)d_in[27];
    const float* pb3  = (const float*)d_in[28];
    const float* fw   = (const float*)d_in[29];
    const float* fb   = (const float*)d_in[30];

    float* out       = (float*)d_out;
    float* out_final = out;                    // [N,128]
    float* out_x3    = out + (size_t)NN * 128; // [N,128]
    float* out_pos   = out + (size_t)NN * 256; // [N,128]

    float *pH, *pX1, *pX2, *pComb, *pP1, *pP2, *pES, *pED;
    int *pCnt;
    uint32_t *pWT;
    cudaGetSymbolAddress((void**)&pH, g_h);
    cudaGetSymbolAddress((void**)&pX1, g_x1);
    cudaGetSymbolAddress((void**)&pX2, g_x2);
    cudaGetSymbolAddress((void**)&pComb, g_comb);
    cudaGetSymbolAddress((void**)&pP1, g_p1);
    cudaGetSymbolAddress((void**)&pP2, g_p2);
    cudaGetSymbolAddress((void**)&pES, g_es);
    cudaGetSymbolAddress((void**)&pED, g_ed);
    cudaGetSymbolAddress((void**)&pCnt, g_cnt);
    cudaGetSymbolAddress((void**)&pWT, g_wt);

    cudaMemsetAsync(pCnt, 0, NN * sizeof(int));

    const int GY = NN / 64;   // 625, exact

    // prep + CSR
    wprep<<<(WT_TOTAL + 255) / 256, 256>>>(W1, W2, W3, pw2, pw3, fw);
    scatter_kernel<<<(ET + 255) / 256, 256>>>(ei);

    // ---- GAT layer 1: Fin=64 -> F=256 (H=4,C=64), scores fused ----
    gemm_nt<<<dim3(4, GY), 128>>>(x, pWT + OFF_W1, nullptr, nullptr, nullptr,
                                  pH, 256, nullptr, 0, NN, 256, 64,
                                  a_s1, a_d1, pES, pED, 4, 64);
    gat_agg<4, 256, 0, 2, 0><<<NN / 4, 256>>>(bg1, ln1g, ln1b, pX1, nullptr);

    // ---- GAT layer 2: Fin=256 -> F=128 (H=2,C=64) ----
    gemm_nt<<<dim3(2, GY), 128>>>(pX1, pWT + OFF_W2, nullptr, nullptr, nullptr,
                                  pH, 128, nullptr, 0, NN, 128, 256,
                                  a_s2, a_d2, pES, pED, 2, 64);
    gat_agg<2, 128, 0, 1, 0><<<NN / 8, 256>>>(bg2, ln2g, ln2b, pX2, nullptr);

    // ---- GAT layer 3: Fin=128 -> F=128 (H=1,C=128): split partial scores ----
    gemm_nt<<<dim3(2, GY), 128>>>(pX2, pWT + OFF_W3, nullptr, nullptr, nullptr,
                                  pH, 128, nullptr, 0, NN, 128, 128,
                                  a_s3, a_d3, pES, pED, 1, 128);
    gat_agg<1, 128, 1, 1, 1><<<NN / 8, 256>>>(bg3, nullptr, nullptr, out_x3, pComb);

    // ---- pointnet ----
    pn1_kernel<<<(NN * 64 + 255) / 256, 256>>>(pos, pw1, pb1, bn1g, bn1b, pP1);
    gemm_nt<<<dim3(2, GY), 128>>>(pP1, pWT + OFF_PW2, pb2, bn2g, bn2b,
                                  pP2, 128, nullptr, 0, NN, 128, 64,
                                  nullptr, nullptr, nullptr, nullptr, 0, 0);
    gemm_nt<<<dim3(2, GY), 128>>>(pP2, pWT + OFF_PW3, pb3, nullptr, nullptr,
                                  out_pos, 128, pComb + 128, 256, NN, 128, 128,
                                  nullptr, nullptr, nullptr, nullptr, 0, 0);

    // ---- fusion ----
    gemm_nt<<<dim3(2, GY), 128>>>(pComb, pWT + OFF_FW, fb, nullptr, nullptr,
                                  out_final, 128, nullptr, 0, NN, 128, 256,
                                  nullptr, nullptr, nullptr, nullptr, 0, 0);
}

// round 15
// speedup vs baseline: 1.0019x; 1.0019x over previous
#include <cuda_runtime.h>
#include <math.h>
#include <stdint.h>

#define NN 40000
#define EE 640000
#define ET 680000   // edges + self loops
#define CAP 128     // padded CSR capacity per node (max observed degree ~35)

// ---------------- scratch (device globals; no allocation) ----------------
__device__ float g_h[NN * 256];      // post-GEMM features of current layer
__device__ float g_x1[NN * 256];
__device__ float g_x2[NN * 128];
__device__ float g_comb[NN * 256];   // [x3 | pos_features]
__device__ float g_p1[NN * 64];
__device__ float g_p2[NN * 128];
__device__ float g_es[NN * 4];
__device__ float g_ed[NN * 4];
__device__ int   g_cnt[NN];
__device__ int   g_srcs[(size_t)NN * CAP];

// ---------------- tf32 helpers ----------------
__device__ __forceinline__ uint32_t f2tf32(float f) {
    uint32_t u;
    asm("cvt.rna.tf32.f32 %0, %1;" : "=r"(u) : "f"(f));
    return u;
}

__device__ __forceinline__ void mma_tf32(float& c0, float& c1, float& c2, float& c3,
                                         uint32_t a0, uint32_t a1, uint32_t a2, uint32_t a3,
                                         uint32_t b0, uint32_t b1) {
    asm volatile(
        "mma.sync.aligned.m16n8k8.row.col.f32.tf32.tf32.f32 "
        "{%0,%1,%2,%3}, {%4,%5,%6,%7}, {%8,%9}, {%0,%1,%2,%3};\n"
        : "+f"(c0), "+f"(c1), "+f"(c2), "+f"(c3)
        : "r"(a0), "r"(a1), "r"(a2), "r"(a3), "r"(b0), "r"(b1));
}

// k-pair interleaved physical column: (k, k+4) become adjacent words
__device__ __forceinline__ int kphys(int kk) {
    return ((kk >> 3) << 3) | ((kk & 3) << 1) | ((kk >> 2) & 1);
}

// ---------------- GEMM (tf32 tensor core): C[n,m] = A[n,k] @ B[m,k]^T ------
// 64x64 CTA tile, 128 threads / 4 warps, warp = 16 rows x 64 cols (R11 config).
// headC==128 writes per-block partial scores to es[r*2+slot] (no atomics).
#define SMS 20   // smem row stride (words)
__global__ void __launch_bounds__(128)
gemm_nt(const float* __restrict__ A, const float* __restrict__ B,
        const float* __restrict__ bias,
        const float* __restrict__ bng, const float* __restrict__ bnb,
        float* __restrict__ C, int ldc,
        float* __restrict__ C2, int ldc2,
        int n, int m, int k,
        const float* __restrict__ a_sf, const float* __restrict__ a_df,
        float* __restrict__ es, float* __restrict__ ed, int H, int headC) {
    __shared__ uint32_t As[2][64][SMS];
    __shared__ uint32_t Bs[2][64][SMS];
    const int tid = threadIdx.x;
    const int rowBase = blockIdx.y * 64;
    const int colBase = blockIdx.x * 64;
    const int lr = tid >> 2;           // 0..31 (+32)
    const int lc = (tid & 3) * 4;      // 0,4,8,12
    const int warp = tid >> 5;
    const int lane = tid & 31;
    const int g = lane >> 2;
    const int tg = lane & 3;
    const int wrow = warp * 16;

    float c[8][4];
    #pragma unroll
    for (int t = 0; t < 8; t++)
        #pragma unroll
        for (int q = 0; q < 4; q++) c[t][q] = 0.f;

    float4 av[2], bv[2];
    #pragma unroll
    for (int h = 0; h < 2; h++) {
        av[h] = *(const float4*)(A + (size_t)(rowBase + lr + h * 32) * k + lc);
        bv[h] = *(const float4*)(B + (size_t)(colBase + lr + h * 32) * k + lc);
    }
    #pragma unroll
    for (int h = 0; h < 2; h++) {
        int rr = lr + h * 32;
        As[0][rr][kphys(lc + 0)] = f2tf32(av[h].x); As[0][rr][kphys(lc + 1)] = f2tf32(av[h].y);
        As[0][rr][kphys(lc + 2)] = f2tf32(av[h].z); As[0][rr][kphys(lc + 3)] = f2tf32(av[h].w);
        Bs[0][rr][kphys(lc + 0)] = f2tf32(bv[h].x); Bs[0][rr][kphys(lc + 1)] = f2tf32(bv[h].y);
        Bs[0][rr][kphys(lc + 2)] = f2tf32(bv[h].z); Bs[0][rr][kphys(lc + 3)] = f2tf32(bv[h].w);
    }
    __syncthreads();

    int st = 0;
    const int T = k / 16;
    for (int it = 0; it < T; it++) {
        bool hasNext = (it + 1) < T;
        if (hasNext) {
            int k0 = (it + 1) * 16;
            #pragma unroll
            for (int h = 0; h < 2; h++) {
                av[h] = *(const float4*)(A + (size_t)(rowBase + lr + h * 32) * k + k0 + lc);
                bv[h] = *(const float4*)(B + (size_t)(colBase + lr + h * 32) * k + k0 + lc);
            }
        }
        #pragma unroll
        for (int kc = 0; kc < 16; kc += 8) {
            const int kb = kc + 2 * tg;
            uint2 aP0 = *(const uint2*)&As[st][wrow + g][kb];
            uint2 aP1 = *(const uint2*)&As[st][wrow + g + 8][kb];
            #pragma unroll
            for (int t = 0; t < 8; t++) {
                uint2 bP = *(const uint2*)&Bs[st][t * 8 + g][kb];
                mma_tf32(c[t][0], c[t][1], c[t][2], c[t][3],
                         aP0.x, aP1.x, aP0.y, aP1.y, bP.x, bP.y);
            }
        }
        if (hasNext) {
            int ns = st ^ 1;
            #pragma unroll
            for (int h = 0; h < 2; h++) {
                int rr = lr + h * 32;
                As[ns][rr][kphys(lc + 0)] = f2tf32(av[h].x); As[ns][rr][kphys(lc + 1)] = f2tf32(av[h].y);
                As[ns][rr][kphys(lc + 2)] = f2tf32(av[h].z); As[ns][rr][kphys(lc + 3)] = f2tf32(av[h].w);
                Bs[ns][rr][kphys(lc + 0)] = f2tf32(bv[h].x); Bs[ns][rr][kphys(lc + 1)] = f2tf32(bv[h].y);
                Bs[ns][rr][kphys(lc + 2)] = f2tf32(bv[h].z); Bs[ns][rr][kphys(lc + 3)] = f2tf32(bv[h].w);
            }
            __syncthreads();
            st = ns;
        }
    }

    // main store epilogue: rows wrow+g(+8), cols t*8+2tg(+1)
    const float inv = rsqrtf(1.f + 1e-5f);
    #pragma unroll
    for (int rr = 0; rr < 2; rr++) {
        int r = rowBase + wrow + g + rr * 8;
        #pragma unroll
        for (int t = 0; t < 8; t++) {
            int c0i = colBase + t * 8 + 2 * tg;
            float v0 = c[t][rr * 2 + 0];
            float v1 = c[t][rr * 2 + 1];
            if (bias) { v0 += bias[c0i]; v1 += bias[c0i + 1]; }
            if (bng) {
                v0 = v0 * (bng[c0i] * inv) + bnb[c0i];
                v1 = v1 * (bng[c0i + 1] * inv) + bnb[c0i + 1];
                v0 = v0 > 0.f ? v0 : 0.f;
                v1 = v1 > 0.f ? v1 : 0.f;
            }
            float2 o2 = make_float2(v0, v1);
            *(float2*)(C + (size_t)r * ldc + c0i) = o2;
            if (C2) *(float2*)(C2 + (size_t)r * ldc2 + c0i) = o2;
        }
    }

    // fused attention scores (raw accumulator dotted with a_s / a_d)
    if (es) {
        #pragma unroll
        for (int rr = 0; rr < 2; rr++) {
            float sv = 0.f, dv = 0.f;
            #pragma unroll
            for (int t = 0; t < 8; t++) {
                int c0i = colBase + t * 8 + 2 * tg;
                sv += c[t][rr * 2] * a_sf[c0i] + c[t][rr * 2 + 1] * a_sf[c0i + 1];
                dv += c[t][rr * 2] * a_df[c0i] + c[t][rr * 2 + 1] * a_df[c0i + 1];
            }
            #pragma unroll
            for (int o = 1; o < 4; o <<= 1) {
                sv += __shfl_xor_sync(0xffffffffu, sv, o);
                dv += __shfl_xor_sync(0xffffffffu, dv, o);
            }
            if (tg == 0) {
                int r = rowBase + wrow + g + rr * 8;
                if (headC == 64) {
                    int h0 = colBase >> 6;
                    es[r * H + h0] = sv;
                    ed[r * H + h0] = dv;
                } else {
                    // headC == 128: each 64-col block writes its own partial slot
                    int slot = colBase >> 6;   // 0 or 1
                    es[r * 2 + slot] = sv;
                    ed[r * 2 + slot] = dv;
                }
            }
        }
    }
}

// ---------------- padded CSR build ----------------
__global__ void scatter_kernel(const int* __restrict__ ei) {
    int e = blockIdx.x * blockDim.x + threadIdx.x;
    if (e >= ET) return;
    int sN, d;
    if (e < EE) { sN = ei[e]; d = ei[EE + e]; } else { sN = d = e - EE; }
    int pos = atomicAdd(&g_cnt[d], 1);
    if (pos < CAP) g_srcs[(size_t)d * CAP + pos] = sN;
}

// ---------------- GAT aggregate + softmax + epilogue ----------------------
// SPLIT=1 (layer 3): scores are two partials es[2r]+es[2r+1].
template<int H, int F, int MODE, int WPN, int SPLIT>
__global__ void gat_agg(const float* __restrict__ bias,
                        const float* __restrict__ lng, const float* __restrict__ lnb,
                        float* __restrict__ out, float* __restrict__ out2) {
    constexpr int HW = H / WPN;
    constexpr int C = F / H;
    constexpr int NPB = 8 / WPN;
    __shared__ float ssum[8], ssum2[8];

    const int lane = threadIdx.x & 31;
    const int warp = threadIdx.x >> 5;
    const int node = blockIdx.x * NPB + warp / WPN;
    const int half = warp % WPN;
    const int colOff = half * 128;
    const int hbase = colOff / C;
    const int hl = (4 * lane) / C;

    const int cnt = min(g_cnt[node], CAP);
    float edn[HW];
    if (SPLIT) {
        edn[0] = g_ed[node * 2] + g_ed[node * 2 + 1];
    } else {
        #pragma unroll
        for (int h = 0; h < HW; h++) edn[h] = g_ed[node * H + hbase + h];
    }

    float4 acc0 = make_float4(0.f, 0.f, 0.f, 0.f);
    float4 acc1 = make_float4(0.f, 0.f, 0.f, 0.f);
    float dl[HW];
    #pragma unroll
    for (int h = 0; h < HW; h++) dl[h] = 0.f;

    const int* __restrict__ srcs = g_srcs + (size_t)node * CAP;

    for (int base = 0; base < cnt; base += 32) {
        int j = base + lane;
        int sj = 0;
        float w[HW];
        #pragma unroll
        for (int h = 0; h < HW; h++) w[h] = 0.f;
        if (j < cnt) {
            sj = srcs[j];
            #pragma unroll
            for (int h = 0; h < HW; h++) {
                float esv = SPLIT ? (g_es[sj * 2] + g_es[sj * 2 + 1])
                                  : g_es[sj * H + hbase + h];
                float v = esv + edn[h];
                v = v > 0.f ? v : 0.2f * v;
                w[h] = expf(v);
                dl[h] += w[h];
            }
        }
        int lim = min(32, cnt - base);
        int jj = 0;
        #pragma unroll 2
        for (; jj + 1 < lim; jj += 2) {
            int sb0 = __shfl_sync(0xffffffffu, sj, jj);
            int sb1 = __shfl_sync(0xffffffffu, sj, jj + 1);
            float ww0, ww1;
            {
                float wb0[HW], wb1[HW];
                #pragma unroll
                for (int h = 0; h < HW; h++) {
                    wb0[h] = __shfl_sync(0xffffffffu, w[h], jj);
                    wb1[h] = __shfl_sync(0xffffffffu, w[h], jj + 1);
                }
                ww0 = wb0[0]; ww1 = wb1[0];
                #pragma unroll
                for (int h = 1; h < HW; h++) {
                    if (hl == h) { ww0 = wb0[h]; ww1 = wb1[h]; }
                }
            }
            float4 hv0 = *(const float4*)(g_h + (size_t)sb0 * F + colOff + 4 * lane);
            float4 hv1 = *(const float4*)(g_h + (size_t)sb1 * F + colOff + 4 * lane);
            acc0.x += ww0 * hv0.x; acc0.y += ww0 * hv0.y;
            acc0.z += ww0 * hv0.z; acc0.w += ww0 * hv0.w;
            acc1.x += ww1 * hv1.x; acc1.y += ww1 * hv1.y;
            acc1.z += ww1 * hv1.z; acc1.w += ww1 * hv1.w;
        }
        if (jj < lim) {
            int sb0 = __shfl_sync(0xffffffffu, sj, jj);
            float wb0[HW];
            #pragma unroll
            for (int h = 0; h < HW; h++) wb0[h] = __shfl_sync(0xffffffffu, w[h], jj);
            float ww0 = wb0[0];
            #pragma unroll
            for (int h = 1; h < HW; h++) if (hl == h) ww0 = wb0[h];
            float4 hv0 = *(const float4*)(g_h + (size_t)sb0 * F + colOff + 4 * lane);
            acc0.x += ww0 * hv0.x; acc0.y += ww0 * hv0.y;
            acc0.z += ww0 * hv0.z; acc0.w += ww0 * hv0.w;
        }
    }
    acc0.x += acc1.x; acc0.y += acc1.y; acc0.z += acc1.z; acc0.w += acc1.w;

    #pragma unroll
    for (int h = 0; h < HW; h++) {
        #pragma unroll
        for (int o = 16; o > 0; o >>= 1)
            dl[h] += __shfl_xor_sync(0xffffffffu, dl[h], o);
    }

    float dsel = dl[0];
    #pragma unroll
    for (int h = 1; h < HW; h++) if (hl == h) dsel = dl[h];
    float dinv = 1.f / (dsel + 1e-16f);
    const int col = colOff + 4 * lane;
    float4 b4 = *(const float4*)(bias + col);
    float res[4];
    res[0] = acc0.x * dinv + b4.x;
    res[1] = acc0.y * dinv + b4.y;
    res[2] = acc0.z * dinv + b4.z;
    res[3] = acc0.w * dinv + b4.w;

    if (MODE == 0) {
        float s = 0.f, s2 = 0.f;
        #pragma unroll
        for (int q = 0; q < 4; q++) { s += res[q]; s2 += res[q] * res[q]; }
        #pragma unroll
        for (int o = 16; o > 0; o >>= 1) {
            s  += __shfl_xor_sync(0xffffffffu, s, o);
            s2 += __shfl_xor_sync(0xffffffffu, s2, o);
        }
        if (WPN == 2) {
            if (lane == 0) { ssum[warp] = s; ssum2[warp] = s2; }
            __syncthreads();
            s += ssum[warp ^ 1];
            s2 += ssum2[warp ^ 1];
        }
        float mu = s / F;
        float var = s2 / F - mu * mu;
        float rstd = rsqrtf(var + 1e-5f);
        float4 g4 = *(const float4*)(lng + col);
        float4 bb4 = *(const float4*)(lnb + col);
        float4 o4;
        o4.x = (res[0] - mu) * rstd * g4.x + bb4.x;
        o4.y = (res[1] - mu) * rstd * g4.y + bb4.y;
        o4.z = (res[2] - mu) * rstd * g4.z + bb4.z;
        o4.w = (res[3] - mu) * rstd * g4.w + bb4.w;
        o4.x = o4.x > 0.f ? o4.x : 0.f;
        o4.y = o4.y > 0.f ? o4.y : 0.f;
        o4.z = o4.z > 0.f ? o4.z : 0.f;
        o4.w = o4.w > 0.f ? o4.w : 0.f;
        *(float4*)(out + (size_t)node * F + col) = o4;
    } else {
        float4 o4 = make_float4(res[0], res[1], res[2], res[3]);
        *(float4*)(out + (size_t)node * F + col) = o4;
        *(float4*)(out2 + (size_t)node * 256 + col) = o4;
    }
}

// ---------------- pointnet layer 1: pos[N,3] -> p1[N,64] with BN+ReLU ------
__global__ void pn1_kernel(const float* __restrict__ pos,
                           const float* __restrict__ pw1, const float* __restrict__ pb1,
                           const float* __restrict__ bn1g, const float* __restrict__ bn1b,
                           float* __restrict__ p1) {
    int i = blockIdx.x * blockDim.x + threadIdx.x;
    if (i >= NN * 64) return;
    int node = i >> 6, c = i & 63;
    float px = pos[node * 3 + 0], py = pos[node * 3 + 1], pz = pos[node * 3 + 2];
    float s = pb1[c] + pw1[c * 3 + 0] * px + pw1[c * 3 + 1] * py + pw1[c * 3 + 2] * pz;
    const float inv = rsqrtf(1.f + 1e-5f);
    s = s * (bn1g[c] * inv) + bn1b[c];
    p1[i] = s > 0.f ? s : 0.f;
}

// ---------------- host ----------------
extern "C" void kernel_launch(void* const* d_in, const int* in_sizes, int n_in,
                              void* d_out, int out_size) {
    const float* x    = (const float*)d_in[0];
    const int*   ei   = (const int*)d_in[1];
    const float* pos  = (const float*)d_in[2];
    const float* W1   = (const float*)d_in[3];
    const float* a_s1 = (const float*)d_in[4];
    const float* a_d1 = (const float*)d_in[5];
    const float* bg1  = (const float*)d_in[6];
    const float* ln1g = (const float*)d_in[7];
    const float* ln1b = (const float*)d_in[8];
    const float* W2   = (const float*)d_in[9];
    const float* a_s2 = (const float*)d_in[10];
    const float* a_d2 = (const float*)d_in[11];
    const float* bg2  = (const float*)d_in[12];
    const float* ln2g = (const float*)d_in[13];
    const float* ln2b = (const float*)d_in[14];
    const float* W3   = (const float*)d_in[15];
    const float* a_s3 = (const float*)d_in[16];
    const float* a_d3 = (const float*)d_in[17];
    const float* bg3  = (const float*)d_in[18];
    const float* pw1  = (const float*)d_in[19];
    const float* pb1  = (const float*)d_in[20];
    const float* bn1g = (const float*)d_in[21];
    const float* bn1b = (const float*)d_in[22];
    const float* pw2  = (const float*)d_in[23];
    const float* pb2  = (const float*)d_in[24];
    const float* bn2g = (const float*)d_in[25];
    const float* bn2b = (const float*)d_in[26];
    const float* pw3  = (const float*)d_in[27];
    const float* pb3  = (const float*)d_in[28];
    const float* fw   = (const float*)d_in[29];
    const float* fb   = (const float*)d_in[30];

    float* out       = (float*)d_out;
    float* out_final = out;                    // [N,128]
    float* out_x3    = out + (size_t)NN * 128; // [N,128]
    float* out_pos   = out + (size_t)NN * 256; // [N,128]

    float *pH, *pX1, *pX2, *pComb, *pP1, *pP2, *pES, *pED;
    int *pCnt;
    cudaGetSymbolAddress((void**)&pH, g_h);
    cudaGetSymbolAddress((void**)&pX1, g_x1);
    cudaGetSymbolAddress((void**)&pX2, g_x2);
    cudaGetSymbolAddress((void**)&pComb, g_comb);
    cudaGetSymbolAddress((void**)&pP1, g_p1);
    cudaGetSymbolAddress((void**)&pP2, g_p2);
    cudaGetSymbolAddress((void**)&pES, g_es);
    cudaGetSymbolAddress((void**)&pED, g_ed);
    cudaGetSymbolAddress((void**)&pCnt, g_cnt);

    cudaMemsetAsync(pCnt, 0, NN * sizeof(int));

    const int GY = NN / 64;   // 625, exact

    // k1
    scatter_kernel<<<(ET + 255) / 256, 256>>>(ei);

    // ---- GAT layer 1: Fin=64 -> F=256 (H=4,C=64), scores fused ----
    gemm_nt<<<dim3(4, GY), 128>>>(x, W1, nullptr, nullptr, nullptr,
                                  pH, 256, nullptr, 0, NN, 256, 64,
                                  a_s1, a_d1, pES, pED, 4, 64);                 // k2
    gat_agg<4, 256, 0, 2, 0><<<NN / 4, 256>>>(bg1, ln1g, ln1b, pX1, nullptr);  // k3

    // ---- GAT layer 2: Fin=256 -> F=128 (H=2,C=64) ----
    gemm_nt<<<dim3(2, GY), 128>>>(pX1, W2, nullptr, nullptr, nullptr,
                                  pH, 128, nullptr, 0, NN, 128, 256,
                                  a_s2, a_d2, pES, pED, 2, 64);                 // k4 <- profiled
    gat_agg<2, 128, 0, 1, 0><<<NN / 8, 256>>>(bg2, ln2g, ln2b, pX2, nullptr);

    // ---- GAT layer 3: Fin=128 -> F=128 (H=1,C=128): split partial scores ----
    gemm_nt<<<dim3(2, GY), 128>>>(pX2, W3, nullptr, nullptr, nullptr,
                                  pH, 128, nullptr, 0, NN, 128, 128,
                                  a_s3, a_d3, pES, pED, 1, 128);
    gat_agg<1, 128, 1, 1, 1><<<NN / 8, 256>>>(bg3, nullptr, nullptr, out_x3, pComb);

    // ---- pointnet ----
    pn1_kernel<<<(NN * 64 + 255) / 256, 256>>>(pos, pw1, pb1, bn1g, bn1b, pP1);
    gemm_nt<<<dim3(2, GY), 128>>>(pP1, pw2, pb2, bn2g, bn2b,
                                  pP2, 128, nullptr, 0, NN, 128, 64,
                                  nullptr, nullptr, nullptr, nullptr, 0, 0);
    gemm_nt<<<dim3(2, GY), 128>>>(pP2, pw3, pb3, nullptr, nullptr,
                                  out_pos, 128, pComb + 128, 256, NN, 128, 128,
                                  nullptr, nullptr, nullptr, nullptr, 0, 0);

    // ---- fusion ----
    gemm_nt<<<dim3(2, GY), 128>>>(pComb, fw, fb, nullptr, nullptr,
                                  out_final, 128, nullptr, 0, NN, 128, 256,
                                  nullptr, nullptr, nullptr, nullptr, 0, 0);
}

// round 16
// speedup vs baseline: 1.1057x; 1.1036x over previous
#include <cuda_runtime.h>
#include <math.h>
#include <stdint.h>

#define NN 40000
#define EE 640000
#define ET 680000   // edges + self loops
#define CAP 128     // padded CSR capacity per node (max observed degree ~35)

// ---------------- scratch (device globals; no allocation) ----------------
__device__ float g_h[NN * 256];      // post-GEMM features of current layer
__device__ float g_x1[NN * 256];
__device__ float g_x2[NN * 128];
__device__ float g_comb[NN * 256];   // [x3 | pos_features]
__device__ float g_p1[NN * 64];
__device__ float g_p2[NN * 128];
__device__ float g_es[NN * 4];
__device__ float g_ed[NN * 4];
__device__ int   g_cnt[NN];
__device__ int   g_srcs[(size_t)NN * CAP];

// ---------------- tf32 helpers ----------------
__device__ __forceinline__ uint32_t f2tf32(float f) {
    uint32_t u;
    asm("cvt.rna.tf32.f32 %0, %1;" : "=r"(u) : "f"(f));
    return u;
}

__device__ __forceinline__ void mma_tf32(float& c0, float& c1, float& c2, float& c3,
                                         uint32_t a0, uint32_t a1, uint32_t a2, uint32_t a3,
                                         uint32_t b0, uint32_t b1) {
    asm volatile(
        "mma.sync.aligned.m16n8k8.row.col.f32.tf32.tf32.f32 "
        "{%0,%1,%2,%3}, {%4,%5,%6,%7}, {%8,%9}, {%0,%1,%2,%3};\n"
        : "+f"(c0), "+f"(c1), "+f"(c2), "+f"(c3)
        : "r"(a0), "r"(a1), "r"(a2), "r"(a3), "r"(b0), "r"(b1));
}

// ---------------- GEMM (tf32 tensor core): C[n,m] = A[n,k] @ B[m,k]^T ------
// EXACT R11 configuration: 64x64 CTA tile, 128 threads / 4 warps,
// warp = 16 rows x 64 cols, plain smem layout, scalar LDS fragment loads.
// headC==128 writes per-block partial scores to es[r*2+slot] (no atomics).
#define SMS 20   // smem row stride (words): 20r+c covers 32 distinct banks
__global__ void __launch_bounds__(128)
gemm_nt(const float* __restrict__ A, const float* __restrict__ B,
        const float* __restrict__ bias,
        const float* __restrict__ bng, const float* __restrict__ bnb,
        float* __restrict__ C, int ldc,
        float* __restrict__ C2, int ldc2,
        int n, int m, int k,
        const float* __restrict__ a_sf, const float* __restrict__ a_df,
        float* __restrict__ es, float* __restrict__ ed, int H, int headC) {
    const int BK = 16;
    __shared__ uint32_t As[2][64][SMS];
    __shared__ uint32_t Bs[2][64][SMS];
    const int tid = threadIdx.x;
    const int rowBase = blockIdx.y * 64;
    const int colBase = blockIdx.x * 64;
    const int lr = tid >> 2;           // 0..31 (+32)
    const int lc = (tid & 3) * 4;      // 0,4,8,12
    const int warp = tid >> 5;         // 0..3
    const int lane = tid & 31;
    const int g = lane >> 2;           // group 0..7
    const int tg = lane & 3;           // thread-in-group
    const int wrow = warp * 16;

    float c[8][4];
    #pragma unroll
    for (int t = 0; t < 8; t++)
        #pragma unroll
        for (int q = 0; q < 4; q++) c[t][q] = 0.f;

    float4 av[2], bv[2];
    #pragma unroll
    for (int h = 0; h < 2; h++) {
        av[h] = *(const float4*)(A + (size_t)(rowBase + lr + h * 32) * k + lc);
        bv[h] = *(const float4*)(B + (size_t)(colBase + lr + h * 32) * k + lc);
    }
    #pragma unroll
    for (int h = 0; h < 2; h++) {
        int rr = lr + h * 32;
        As[0][rr][lc + 0] = f2tf32(av[h].x); As[0][rr][lc + 1] = f2tf32(av[h].y);
        As[0][rr][lc + 2] = f2tf32(av[h].z); As[0][rr][lc + 3] = f2tf32(av[h].w);
        Bs[0][rr][lc + 0] = f2tf32(bv[h].x); Bs[0][rr][lc + 1] = f2tf32(bv[h].y);
        Bs[0][rr][lc + 2] = f2tf32(bv[h].z); Bs[0][rr][lc + 3] = f2tf32(bv[h].w);
    }
    __syncthreads();

    int s = 0;
    const int T = k / BK;
    for (int it = 0; it < T; it++) {
        bool hasNext = (it + 1) < T;
        if (hasNext) {
            int k0 = (it + 1) * BK;
            #pragma unroll
            for (int h = 0; h < 2; h++) {
                av[h] = *(const float4*)(A + (size_t)(rowBase + lr + h * 32) * k + k0 + lc);
                bv[h] = *(const float4*)(B + (size_t)(colBase + lr + h * 32) * k + k0 + lc);
            }
        }
        #pragma unroll
        for (int kc = 0; kc < 16; kc += 8) {
            uint32_t a0 = As[s][wrow + g][kc + tg];
            uint32_t a1 = As[s][wrow + g + 8][kc + tg];
            uint32_t a2 = As[s][wrow + g][kc + tg + 4];
            uint32_t a3 = As[s][wrow + g + 8][kc + tg + 4];
            #pragma unroll
            for (int t = 0; t < 8; t++) {
                uint32_t b0 = Bs[s][t * 8 + g][kc + tg];
                uint32_t b1 = Bs[s][t * 8 + g][kc + tg + 4];
                mma_tf32(c[t][0], c[t][1], c[t][2], c[t][3], a0, a1, a2, a3, b0, b1);
            }
        }
        if (hasNext) {
            int ns = s ^ 1;
            #pragma unroll
            for (int h = 0; h < 2; h++) {
                int rr = lr + h * 32;
                As[ns][rr][lc + 0] = f2tf32(av[h].x); As[ns][rr][lc + 1] = f2tf32(av[h].y);
                As[ns][rr][lc + 2] = f2tf32(av[h].z); As[ns][rr][lc + 3] = f2tf32(av[h].w);
                Bs[ns][rr][lc + 0] = f2tf32(bv[h].x); Bs[ns][rr][lc + 1] = f2tf32(bv[h].y);
                Bs[ns][rr][lc + 2] = f2tf32(bv[h].z); Bs[ns][rr][lc + 3] = f2tf32(bv[h].w);
            }
            __syncthreads();
            s = ns;
        }
    }

    // main store epilogue: thread owns rows (wrow+g, wrow+g+8), cols t*8+2tg(+1)
    const float inv = rsqrtf(1.f + 1e-5f);
    #pragma unroll
    for (int rr = 0; rr < 2; rr++) {
        int r = rowBase + wrow + g + rr * 8;
        #pragma unroll
        for (int t = 0; t < 8; t++) {
            int c0i = colBase + t * 8 + 2 * tg;
            float v0 = c[t][rr * 2 + 0];
            float v1 = c[t][rr * 2 + 1];
            if (bias) { v0 += bias[c0i]; v1 += bias[c0i + 1]; }
            if (bng) {
                v0 = v0 * (bng[c0i] * inv) + bnb[c0i];
                v1 = v1 * (bng[c0i + 1] * inv) + bnb[c0i + 1];
                v0 = v0 > 0.f ? v0 : 0.f;
                v1 = v1 > 0.f ? v1 : 0.f;
            }
            float2 o2 = make_float2(v0, v1);
            *(float2*)(C + (size_t)r * ldc + c0i) = o2;
            if (C2) *(float2*)(C2 + (size_t)r * ldc2 + c0i) = o2;
        }
    }

    // fused attention scores (raw accumulator dotted with a_s / a_d)
    if (es) {
        #pragma unroll
        for (int rr = 0; rr < 2; rr++) {
            float sv = 0.f, dv = 0.f;
            #pragma unroll
            for (int t = 0; t < 8; t++) {
                int c0i = colBase + t * 8 + 2 * tg;
                sv += c[t][rr * 2] * a_sf[c0i] + c[t][rr * 2 + 1] * a_sf[c0i + 1];
                dv += c[t][rr * 2] * a_df[c0i] + c[t][rr * 2 + 1] * a_df[c0i + 1];
            }
            // reduce over the 4 lanes of this quad (same row)
            #pragma unroll
            for (int o = 1; o < 4; o <<= 1) {
                sv += __shfl_xor_sync(0xffffffffu, sv, o);
                dv += __shfl_xor_sync(0xffffffffu, dv, o);
            }
            if (tg == 0) {
                int r = rowBase + wrow + g + rr * 8;
                if (headC == 64) {
                    int h0 = colBase >> 6;
                    es[r * H + h0] = sv;
                    ed[r * H + h0] = dv;
                } else {
                    // headC == 128: each 64-col block writes its own partial slot
                    int slot = colBase >> 6;   // 0 or 1
                    es[r * 2 + slot] = sv;
                    ed[r * 2 + slot] = dv;
                }
            }
        }
    }
}

// ---------------- padded CSR build ----------------
__global__ void scatter_kernel(const int* __restrict__ ei) {
    int e = blockIdx.x * blockDim.x + threadIdx.x;
    if (e >= ET) return;
    int sN, d;
    if (e < EE) { sN = ei[e]; d = ei[EE + e]; } else { sN = d = e - EE; }
    int pos = atomicAdd(&g_cnt[d], 1);
    if (pos < CAP) g_srcs[(size_t)d * CAP + pos] = sN;
}

// ---------------- GAT aggregate + softmax + epilogue ----------------------
// SPLIT=1 (layer 3): scores are two partials es[2r]+es[2r+1].
template<int H, int F, int MODE, int WPN, int SPLIT>
__global__ void gat_agg(const float* __restrict__ bias,
                        const float* __restrict__ lng, const float* __restrict__ lnb,
                        float* __restrict__ out, float* __restrict__ out2) {
    constexpr int HW = H / WPN;
    constexpr int C = F / H;
    constexpr int NPB = 8 / WPN;
    __shared__ float ssum[8], ssum2[8];

    const int lane = threadIdx.x & 31;
    const int warp = threadIdx.x >> 5;
    const int node = blockIdx.x * NPB + warp / WPN;
    const int half = warp % WPN;
    const int colOff = half * 128;
    const int hbase = colOff / C;
    const int hl = (4 * lane) / C;

    const int cnt = min(g_cnt[node], CAP);
    float edn[HW];
    if (SPLIT) {
        edn[0] = g_ed[node * 2] + g_ed[node * 2 + 1];
    } else {
        #pragma unroll
        for (int h = 0; h < HW; h++) edn[h] = g_ed[node * H + hbase + h];
    }

    float4 acc0 = make_float4(0.f, 0.f, 0.f, 0.f);
    float4 acc1 = make_float4(0.f, 0.f, 0.f, 0.f);
    float dl[HW];
    #pragma unroll
    for (int h = 0; h < HW; h++) dl[h] = 0.f;

    const int* __restrict__ srcs = g_srcs + (size_t)node * CAP;

    for (int base = 0; base < cnt; base += 32) {
        int j = base + lane;
        int sj = 0;
        float w[HW];
        #pragma unroll
        for (int h = 0; h < HW; h++) w[h] = 0.f;
        if (j < cnt) {
            sj = srcs[j];
            #pragma unroll
            for (int h = 0; h < HW; h++) {
                float esv = SPLIT ? (g_es[sj * 2] + g_es[sj * 2 + 1])
                                  : g_es[sj * H + hbase + h];
                float v = esv + edn[h];
                v = v > 0.f ? v : 0.2f * v;
                w[h] = expf(v);
                dl[h] += w[h];
            }
        }
        int lim = min(32, cnt - base);
        int jj = 0;
        #pragma unroll 2
        for (; jj + 1 < lim; jj += 2) {
            int sb0 = __shfl_sync(0xffffffffu, sj, jj);
            int sb1 = __shfl_sync(0xffffffffu, sj, jj + 1);
            float ww0, ww1;
            {
                float wb0[HW], wb1[HW];
                #pragma unroll
                for (int h = 0; h < HW; h++) {
                    wb0[h] = __shfl_sync(0xffffffffu, w[h], jj);
                    wb1[h] = __shfl_sync(0xffffffffu, w[h], jj + 1);
                }
                ww0 = wb0[0]; ww1 = wb1[0];
                #pragma unroll
                for (int h = 1; h < HW; h++) {
                    if (hl == h) { ww0 = wb0[h]; ww1 = wb1[h]; }
                }
            }
            float4 hv0 = *(const float4*)(g_h + (size_t)sb0 * F + colOff + 4 * lane);
            float4 hv1 = *(const float4*)(g_h + (size_t)sb1 * F + colOff + 4 * lane);
            acc0.x += ww0 * hv0.x; acc0.y += ww0 * hv0.y;
            acc0.z += ww0 * hv0.z; acc0.w += ww0 * hv0.w;
            acc1.x += ww1 * hv1.x; acc1.y += ww1 * hv1.y;
            acc1.z += ww1 * hv1.z; acc1.w += ww1 * hv1.w;
        }
        if (jj < lim) {
            int sb0 = __shfl_sync(0xffffffffu, sj, jj);
            float wb0[HW];
            #pragma unroll
            for (int h = 0; h < HW; h++) wb0[h] = __shfl_sync(0xffffffffu, w[h], jj);
            float ww0 = wb0[0];
            #pragma unroll
            for (int h = 1; h < HW; h++) if (hl == h) ww0 = wb0[h];
            float4 hv0 = *(const float4*)(g_h + (size_t)sb0 * F + colOff + 4 * lane);
            acc0.x += ww0 * hv0.x; acc0.y += ww0 * hv0.y;
            acc0.z += ww0 * hv0.z; acc0.w += ww0 * hv0.w;
        }
    }
    acc0.x += acc1.x; acc0.y += acc1.y; acc0.z += acc1.z; acc0.w += acc1.w;

    #pragma unroll
    for (int h = 0; h < HW; h++) {
        #pragma unroll
        for (int o = 16; o > 0; o >>= 1)
            dl[h] += __shfl_xor_sync(0xffffffffu, dl[h], o);
    }

    float dsel = dl[0];
    #pragma unroll
    for (int h = 1; h < HW; h++) if (hl == h) dsel = dl[h];
    float dinv = 1.f / (dsel + 1e-16f);
    const int col = colOff + 4 * lane;
    float4 b4 = *(const float4*)(bias + col);
    float res[4];
    res[0] = acc0.x * dinv + b4.x;
    res[1] = acc0.y * dinv + b4.y;
    res[2] = acc0.z * dinv + b4.z;
    res[3] = acc0.w * dinv + b4.w;

    if (MODE == 0) {
        float s = 0.f, s2 = 0.f;
        #pragma unroll
        for (int q = 0; q < 4; q++) { s += res[q]; s2 += res[q] * res[q]; }
        #pragma unroll
        for (int o = 16; o > 0; o >>= 1) {
            s  += __shfl_xor_sync(0xffffffffu, s, o);
            s2 += __shfl_xor_sync(0xffffffffu, s2, o);
        }
        if (WPN == 2) {
            if (lane == 0) { ssum[warp] = s; ssum2[warp] = s2; }
            __syncthreads();
            s += ssum[warp ^ 1];
            s2 += ssum2[warp ^ 1];
        }
        float mu = s / F;
        float var = s2 / F - mu * mu;
        float rstd = rsqrtf(var + 1e-5f);
        float4 g4 = *(const float4*)(lng + col);
        float4 bb4 = *(const float4*)(lnb + col);
        float4 o4;
        o4.x = (res[0] - mu) * rstd * g4.x + bb4.x;
        o4.y = (res[1] - mu) * rstd * g4.y + bb4.y;
        o4.z = (res[2] - mu) * rstd * g4.z + bb4.z;
        o4.w = (res[3] - mu) * rstd * g4.w + bb4.w;
        o4.x = o4.x > 0.f ? o4.x : 0.f;
        o4.y = o4.y > 0.f ? o4.y : 0.f;
        o4.z = o4.z > 0.f ? o4.z : 0.f;
        o4.w = o4.w > 0.f ? o4.w : 0.f;
        *(float4*)(out + (size_t)node * F + col) = o4;
    } else {
        float4 o4 = make_float4(res[0], res[1], res[2], res[3]);
        *(float4*)(out + (size_t)node * F + col) = o4;
        *(float4*)(out2 + (size_t)node * 256 + col) = o4;
    }
}

// ---------------- pointnet layer 1: pos[N,3] -> p1[N,64] with BN+ReLU ------
__global__ void pn1_kernel(const float* __restrict__ pos,
                           const float* __restrict__ pw1, const float* __restrict__ pb1,
                           const float* __restrict__ bn1g, const float* __restrict__ bn1b,
                           float* __restrict__ p1) {
    int i = blockIdx.x * blockDim.x + threadIdx.x;
    if (i >= NN * 64) return;
    int node = i >> 6, c = i & 63;
    float px = pos[node * 3 + 0], py = pos[node * 3 + 1], pz = pos[node * 3 + 2];
    float s = pb1[c] + pw1[c * 3 + 0] * px + pw1[c * 3 + 1] * py + pw1[c * 3 + 2] * pz;
    const float inv = rsqrtf(1.f + 1e-5f);
    s = s * (bn1g[c] * inv) + bn1b[c];
    p1[i] = s > 0.f ? s : 0.f;
}

// ---------------- host ----------------
extern "C" void kernel_launch(void* const* d_in, const int* in_sizes, int n_in,
                              void* d_out, int out_size) {
    const float* x    = (const float*)d_in[0];
    const int*   ei   = (const int*)d_in[1];
    const float* pos  = (const float*)d_in[2];
    const float* W1   = (const float*)d_in[3];
    const float* a_s1 = (const float*)d_in[4];
    const float* a_d1 = (const float*)d_in[5];
    const float* bg1  = (const float*)d_in[6];
    const float* ln1g = (const float*)d_in[7];
    const float* ln1b = (const float*)d_in[8];
    const float* W2   = (const float*)d_in[9];
    const float* a_s2 = (const float*)d_in[10];
    const float* a_d2 = (const float*)d_in[11];
    const float* bg2  = (const float*)d_in[12];
    const float* ln2g = (const float*)d_in[13];
    const float* ln2b = (const float*)d_in[14];
    const float* W3   = (const float*)d_in[15];
    const float* a_s3 = (const float*)d_in[16];
    const float* a_d3 = (const float*)d_in[17];
    const float* bg3  = (const float*)d_in[18];
    const float* pw1  = (const float*)d_in[19];
    const float* pb1  = (const float*)d_in[20];
    const float* bn1g = (const float*)d_in[21];
    const float* bn1b = (const float*)d_in[22];
    const float* pw2  = (const float*)d_in[23];
    const float* pb2  = (const float*)d_in[24];
    const float* bn2g = (const float*)d_in[25];
    const float* bn2b = (const float*)d_in[26];
    const float* pw3  = (const float*)d_in[27];
    const float* pb3  = (const float*)d_in[28];
    const float* fw   = (const float*)d_in[29];
    const float* fb   = (const float*)d_in[30];

    float* out       = (float*)d_out;
    float* out_final = out;                    // [N,128]
    float* out_x3    = out + (size_t)NN * 128; // [N,128]
    float* out_pos   = out + (size_t)NN * 256; // [N,128]

    float *pH, *pX1, *pX2, *pComb, *pP1, *pP2, *pES, *pED;
    int *pCnt;
    cudaGetSymbolAddress((void**)&pH, g_h);
    cudaGetSymbolAddress((void**)&pX1, g_x1);
    cudaGetSymbolAddress((void**)&pX2, g_x2);
    cudaGetSymbolAddress((void**)&pComb, g_comb);
    cudaGetSymbolAddress((void**)&pP1, g_p1);
    cudaGetSymbolAddress((void**)&pP2, g_p2);
    cudaGetSymbolAddress((void**)&pES, g_es);
    cudaGetSymbolAddress((void**)&pED, g_ed);
    cudaGetSymbolAddress((void**)&pCnt, g_cnt);

    cudaMemsetAsync(pCnt, 0, NN * sizeof(int));

    const int GY = NN / 64;   // 625, exact

    // k1
    scatter_kernel<<<(ET + 255) / 256, 256>>>(ei);

    // ---- GAT layer 1: Fin=64 -> F=256 (H=4,C=64), scores fused ----
    gemm_nt<<<dim3(4, GY), 128>>>(x, W1, nullptr, nullptr, nullptr,
                                  pH, 256, nullptr, 0, NN, 256, 64,
                                  a_s1, a_d1, pES, pED, 4, 64);                 // k2
    gat_agg<4, 256, 0, 2, 0><<<NN / 4, 256>>>(bg1, ln1g, ln1b, pX1, nullptr);  // k3

    // ---- GAT layer 2: Fin=256 -> F=128 (H=2,C=64) ----
    gemm_nt<<<dim3(2, GY), 128>>>(pX1, W2, nullptr, nullptr, nullptr,
                                  pH, 128, nullptr, 0, NN, 128, 256,
                                  a_s2, a_d2, pES, pED, 2, 64);                 // k4 <- profiled
    gat_agg<2, 128, 0, 1, 0><<<NN / 8, 256>>>(bg2, ln2g, ln2b, pX2, nullptr);

    // ---- GAT layer 3: Fin=128 -> F=128 (H=1,C=128): split partial scores ----
    gemm_nt<<<dim3(2, GY), 128>>>(pX2, W3, nullptr, nullptr, nullptr,
                                  pH, 128, nullptr, 0, NN, 128, 128,
                                  a_s3, a_d3, pES, pED, 1, 128);
    gat_agg<1, 128, 1, 1, 1><<<NN / 8, 256>>>(bg3, nullptr, nullptr, out_x3, pComb);

    // ---- pointnet ----
    pn1_kernel<<<(NN * 64 + 255) / 256, 256>>>(pos, pw1, pb1, bn1g, bn1b, pP1);
    gemm_nt<<<dim3(2, GY), 128>>>(pP1, pw2, pb2, bn2g, bn2b,
                                  pP2, 128, nullptr, 0, NN, 128, 64,
                                  nullptr, nullptr, nullptr, nullptr, 0, 0);
    gemm_nt<<<dim3(2, GY), 128>>>(pP2, pw3, pb3, nullptr, nullptr,
                                  out_pos, 128, pComb + 128, 256, NN, 128, 128,
                                  nullptr, nullptr, nullptr, nullptr, 0, 0);

    // ---- fusion ----
    gemm_nt<<<dim3(2, GY), 128>>>(pComb, fw, fb, nullptr, nullptr,
                                  out_final, 128, nullptr, 0, NN, 128, 256,
                                  nullptr, nullptr, nullptr, nullptr, 0, 0);
}

// round 17
// speedup vs baseline: 1.1125x; 1.0061x over previous
#include <cuda_runtime.h>
#include <math.h>
#include <stdint.h>

#define NN 40000
#define EE 640000
#define ET 680000   // edges + self loops
#define CAP 128     // padded CSR capacity per node (max observed degree ~35)

// ---------------- scratch (device globals; no allocation) ----------------
__device__ float g_h[NN * 256];      // post-GEMM features of current layer
__device__ float g_x1[NN * 256];
__device__ float g_x2[NN * 128];
__device__ float g_comb[NN * 256];   // [x3 | pos_features]
__device__ float g_p1[NN * 64];
__device__ float g_p2[NN * 128];
__device__ float g_es[NN * 4];
__device__ float g_ed[NN * 4];
__device__ int   g_cnt[NN];
__device__ int   g_srcs[(size_t)NN * CAP];

// ---------------- tf32 helpers ----------------
__device__ __forceinline__ uint32_t f2tf32(float f) {
    uint32_t u;
    asm("cvt.rna.tf32.f32 %0, %1;" : "=r"(u) : "f"(f));
    return u;
}

__device__ __forceinline__ void mma_tf32(float& c0, float& c1, float& c2, float& c3,
                                         uint32_t a0, uint32_t a1, uint32_t a2, uint32_t a3,
                                         uint32_t b0, uint32_t b1) {
    asm volatile(
        "mma.sync.aligned.m16n8k8.row.col.f32.tf32.tf32.f32 "
        "{%0,%1,%2,%3}, {%4,%5,%6,%7}, {%8,%9}, {%0,%1,%2,%3};\n"
        : "+f"(c0), "+f"(c1), "+f"(c2), "+f"(c3)
        : "r"(a0), "r"(a1), "r"(a2), "r"(a3), "r"(b0), "r"(b1));
}

// ---------------- GEMM job descriptor ----------------
struct GemmJob {
    const float* A; const float* B;
    const float* bias; const float* bng; const float* bnb;
    float* C; int ldc;
    float* C2; int ldc2;
    int n, m, k;
    const float* a_sf; const float* a_df;
    float* es; float* ed; int H, headC;
    int gx;   // grid x extent for this job (m/64)
};

// ---------------- GEMM body (R11 config): C[n,m] = A[n,k] @ B[m,k]^T -------
// 64x64 CTA tile, 128 threads / 4 warps, warp = 16 rows x 64 cols,
// plain smem layout, scalar LDS fragment loads, double buffered.
// headC==128 writes per-block partial scores to es[r*2+slot] (no atomics).
#define SMS 20   // smem row stride (words): 20r+c covers 32 distinct banks
__device__ __forceinline__ void gemm_body(const GemmJob& J) {
    __shared__ uint32_t As[2][64][SMS];
    __shared__ uint32_t Bs[2][64][SMS];
    const float* __restrict__ A = J.A;
    const float* __restrict__ B = J.B;
    const int k = J.k;
    const int tid = threadIdx.x;
    const int rowBase = blockIdx.y * 64;
    const int colBase = blockIdx.x * 64;
    const int lr = tid >> 2;           // 0..31 (+32)
    const int lc = (tid & 3) * 4;      // 0,4,8,12
    const int warp = tid >> 5;         // 0..3
    const int lane = tid & 31;
    const int g = lane >> 2;           // group 0..7
    const int tg = lane & 3;           // thread-in-group
    const int wrow = warp * 16;

    float c[8][4];
    #pragma unroll
    for (int t = 0; t < 8; t++)
        #pragma unroll
        for (int q = 0; q < 4; q++) c[t][q] = 0.f;

    float4 av[2], bv[2];
    #pragma unroll
    for (int h = 0; h < 2; h++) {
        av[h] = *(const float4*)(A + (size_t)(rowBase + lr + h * 32) * k + lc);
        bv[h] = *(const float4*)(B + (size_t)(colBase + lr + h * 32) * k + lc);
    }
    #pragma unroll
    for (int h = 0; h < 2; h++) {
        int rr = lr + h * 32;
        As[0][rr][lc + 0] = f2tf32(av[h].x); As[0][rr][lc + 1] = f2tf32(av[h].y);
        As[0][rr][lc + 2] = f2tf32(av[h].z); As[0][rr][lc + 3] = f2tf32(av[h].w);
        Bs[0][rr][lc + 0] = f2tf32(bv[h].x); Bs[0][rr][lc + 1] = f2tf32(bv[h].y);
        Bs[0][rr][lc + 2] = f2tf32(bv[h].z); Bs[0][rr][lc + 3] = f2tf32(bv[h].w);
    }
    __syncthreads();

    int s = 0;
    const int T = k / 16;
    for (int it = 0; it < T; it++) {
        bool hasNext = (it + 1) < T;
        if (hasNext) {
            int k0 = (it + 1) * 16;
            #pragma unroll
            for (int h = 0; h < 2; h++) {
                av[h] = *(const float4*)(A + (size_t)(rowBase + lr + h * 32) * k + k0 + lc);
                bv[h] = *(const float4*)(B + (size_t)(colBase + lr + h * 32) * k + k0 + lc);
            }
        }
        #pragma unroll
        for (int kc = 0; kc < 16; kc += 8) {
            uint32_t a0 = As[s][wrow + g][kc + tg];
            uint32_t a1 = As[s][wrow + g + 8][kc + tg];
            uint32_t a2 = As[s][wrow + g][kc + tg + 4];
            uint32_t a3 = As[s][wrow + g + 8][kc + tg + 4];
            #pragma unroll
            for (int t = 0; t < 8; t++) {
                uint32_t b0 = Bs[s][t * 8 + g][kc + tg];
                uint32_t b1 = Bs[s][t * 8 + g][kc + tg + 4];
                mma_tf32(c[t][0], c[t][1], c[t][2], c[t][3], a0, a1, a2, a3, b0, b1);
            }
        }
        if (hasNext) {
            int ns = s ^ 1;
            #pragma unroll
            for (int h = 0; h < 2; h++) {
                int rr = lr + h * 32;
                As[ns][rr][lc + 0] = f2tf32(av[h].x); As[ns][rr][lc + 1] = f2tf32(av[h].y);
                As[ns][rr][lc + 2] = f2tf32(av[h].z); As[ns][rr][lc + 3] = f2tf32(av[h].w);
                Bs[ns][rr][lc + 0] = f2tf32(bv[h].x); Bs[ns][rr][lc + 1] = f2tf32(bv[h].y);
                Bs[ns][rr][lc + 2] = f2tf32(bv[h].z); Bs[ns][rr][lc + 3] = f2tf32(bv[h].w);
            }
            __syncthreads();
            s = ns;
        }
    }

    // main store epilogue: thread owns rows (wrow+g, wrow+g+8), cols t*8+2tg(+1)
    const float inv = rsqrtf(1.f + 1e-5f);
    #pragma unroll
    for (int rr = 0; rr < 2; rr++) {
        int r = rowBase + wrow + g + rr * 8;
        #pragma unroll
        for (int t = 0; t < 8; t++) {
            int c0i = colBase + t * 8 + 2 * tg;
            float v0 = c[t][rr * 2 + 0];
            float v1 = c[t][rr * 2 + 1];
            if (J.bias) { v0 += J.bias[c0i]; v1 += J.bias[c0i + 1]; }
            if (J.bng) {
                v0 = v0 * (J.bng[c0i] * inv) + J.bnb[c0i];
                v1 = v1 * (J.bng[c0i + 1] * inv) + J.bnb[c0i + 1];
                v0 = v0 > 0.f ? v0 : 0.f;
                v1 = v1 > 0.f ? v1 : 0.f;
            }
            float2 o2 = make_float2(v0, v1);
            *(float2*)(J.C + (size_t)r * J.ldc + c0i) = o2;
            if (J.C2) *(float2*)(J.C2 + (size_t)r * J.ldc2 + c0i) = o2;
        }
    }

    // fused attention scores (raw accumulator dotted with a_s / a_d)
    if (J.es) {
        #pragma unroll
        for (int rr = 0; rr < 2; rr++) {
            float sv = 0.f, dv = 0.f;
            #pragma unroll
            for (int t = 0; t < 8; t++) {
                int c0i = colBase + t * 8 + 2 * tg;
                sv += c[t][rr * 2] * J.a_sf[c0i] + c[t][rr * 2 + 1] * J.a_sf[c0i + 1];
                dv += c[t][rr * 2] * J.a_df[c0i] + c[t][rr * 2 + 1] * J.a_df[c0i + 1];
            }
            #pragma unroll
            for (int o = 1; o < 4; o <<= 1) {
                sv += __shfl_xor_sync(0xffffffffu, sv, o);
                dv += __shfl_xor_sync(0xffffffffu, dv, o);
            }
            if (tg == 0) {
                int r = rowBase + wrow + g + rr * 8;
                if (J.headC == 64) {
                    int h0 = colBase >> 6;
                    J.es[r * J.H + h0] = sv;
                    J.ed[r * J.H + h0] = dv;
                } else {
                    int slot = colBase >> 6;   // 0 or 1
                    J.es[r * 2 + slot] = sv;
                    J.ed[r * 2 + slot] = dv;
                }
            }
        }
    }
}

__global__ void __launch_bounds__(128) gemm_one(GemmJob j0) {
    gemm_body(j0);
}

__global__ void __launch_bounds__(128) gemm_dual(GemmJob j0, GemmJob j1) {
    const GemmJob& J = blockIdx.z ? j1 : j0;
    if ((int)blockIdx.x >= J.gx) return;
    gemm_body(J);
}

// ---------------- merged: padded CSR build + pointnet layer 1 -------------
#define EB ((ET + 255) / 256)
#define PB ((NN * 64 + 255) / 256)
__global__ void prep_kernel(const int* __restrict__ ei,
                            const float* __restrict__ pos,
                            const float* __restrict__ pw1, const float* __restrict__ pb1,
                            const float* __restrict__ bn1g, const float* __restrict__ bn1b,
                            float* __restrict__ p1) {
    int b = blockIdx.x;
    if (b < EB) {
        int e = b * 256 + threadIdx.x;
        if (e >= ET) return;
        int sN, d;
        if (e < EE) { sN = ei[e]; d = ei[EE + e]; } else { sN = d = e - EE; }
        int pos_ = atomicAdd(&g_cnt[d], 1);
        if (pos_ < CAP) g_srcs[(size_t)d * CAP + pos_] = sN;
    } else {
        int i = (b - EB) * 256 + threadIdx.x;
        if (i >= NN * 64) return;
        int node = i >> 6, c = i & 63;
        float px = pos[node * 3 + 0], py = pos[node * 3 + 1], pz = pos[node * 3 + 2];
        float s = pb1[c] + pw1[c * 3 + 0] * px + pw1[c * 3 + 1] * py + pw1[c * 3 + 2] * pz;
        const float inv = rsqrtf(1.f + 1e-5f);
        s = s * (bn1g[c] * inv) + bn1b[c];
        p1[i] = s > 0.f ? s : 0.f;
    }
}

// ---------------- GAT aggregate + softmax + epilogue ----------------------
// SPLIT=1 (layer 3): scores are two partials es[2r]+es[2r+1].
template<int H, int F, int MODE, int WPN, int SPLIT>
__global__ void gat_agg(const float* __restrict__ bias,
                        const float* __restrict__ lng, const float* __restrict__ lnb,
                        float* __restrict__ out, float* __restrict__ out2) {
    constexpr int HW = H / WPN;
    constexpr int C = F / H;
    constexpr int NPB = 8 / WPN;
    __shared__ float ssum[8], ssum2[8];

    const int lane = threadIdx.x & 31;
    const int warp = threadIdx.x >> 5;
    const int node = blockIdx.x * NPB + warp / WPN;
    const int half = warp % WPN;
    const int colOff = half * 128;
    const int hbase = colOff / C;
    const int hl = (4 * lane) / C;

    const int cnt = min(g_cnt[node], CAP);
    float edn[HW];
    if (SPLIT) {
        edn[0] = g_ed[node * 2] + g_ed[node * 2 + 1];
    } else {
        #pragma unroll
        for (int h = 0; h < HW; h++) edn[h] = g_ed[node * H + hbase + h];
    }

    float4 acc0 = make_float4(0.f, 0.f, 0.f, 0.f);
    float4 acc1 = make_float4(0.f, 0.f, 0.f, 0.f);
    float dl[HW];
    #pragma unroll
    for (int h = 0; h < HW; h++) dl[h] = 0.f;

    const int* __restrict__ srcs = g_srcs + (size_t)node * CAP;

    for (int base = 0; base < cnt; base += 32) {
        int j = base + lane;
        int sj = 0;
        float w[HW];
        #pragma unroll
        for (int h = 0; h < HW; h++) w[h] = 0.f;
        if (j < cnt) {
            sj = srcs[j];
            #pragma unroll
            for (int h = 0; h < HW; h++) {
                float esv = SPLIT ? (g_es[sj * 2] + g_es[sj * 2 + 1])
                                  : g_es[sj * H + hbase + h];
                float v = esv + edn[h];
                v = v > 0.f ? v : 0.2f * v;
                w[h] = expf(v);
                dl[h] += w[h];
            }
        }
        int lim = min(32, cnt - base);
        int jj = 0;
        #pragma unroll 2
        for (; jj + 1 < lim; jj += 2) {
            int sb0 = __shfl_sync(0xffffffffu, sj, jj);
            int sb1 = __shfl_sync(0xffffffffu, sj, jj + 1);
            float ww0, ww1;
            {
                float wb0[HW], wb1[HW];
                #pragma unroll
                for (int h = 0; h < HW; h++) {
                    wb0[h] = __shfl_sync(0xffffffffu, w[h], jj);
                    wb1[h] = __shfl_sync(0xffffffffu, w[h], jj + 1);
                }
                ww0 = wb0[0]; ww1 = wb1[0];
                #pragma unroll
                for (int h = 1; h < HW; h++) {
                    if (hl == h) { ww0 = wb0[h]; ww1 = wb1[h]; }
                }
            }
            float4 hv0 = *(const float4*)(g_h + (size_t)sb0 * F + colOff + 4 * lane);
            float4 hv1 = *(const float4*)(g_h + (size_t)sb1 * F + colOff + 4 * lane);
            acc0.x += ww0 * hv0.x; acc0.y += ww0 * hv0.y;
            acc0.z += ww0 * hv0.z; acc0.w += ww0 * hv0.w;
            acc1.x += ww1 * hv1.x; acc1.y += ww1 * hv1.y;
            acc1.z += ww1 * hv1.z; acc1.w += ww1 * hv1.w;
        }
        if (jj < lim) {
            int sb0 = __shfl_sync(0xffffffffu, sj, jj);
            float wb0[HW];
            #pragma unroll
            for (int h = 0; h < HW; h++) wb0[h] = __shfl_sync(0xffffffffu, w[h], jj);
            float ww0 = wb0[0];
            #pragma unroll
            for (int h = 1; h < HW; h++) if (hl == h) ww0 = wb0[h];
            float4 hv0 = *(const float4*)(g_h + (size_t)sb0 * F + colOff + 4 * lane);
            acc0.x += ww0 * hv0.x; acc0.y += ww0 * hv0.y;
            acc0.z += ww0 * hv0.z; acc0.w += ww0 * hv0.w;
        }
    }
    acc0.x += acc1.x; acc0.y += acc1.y; acc0.z += acc1.z; acc0.w += acc1.w;

    #pragma unroll
    for (int h = 0; h < HW; h++) {
        #pragma unroll
        for (int o = 16; o > 0; o >>= 1)
            dl[h] += __shfl_xor_sync(0xffffffffu, dl[h], o);
    }

    float dsel = dl[0];
    #pragma unroll
    for (int h = 1; h < HW; h++) if (hl == h) dsel = dl[h];
    float dinv = 1.f / (dsel + 1e-16f);
    const int col = colOff + 4 * lane;
    float4 b4 = *(const float4*)(bias + col);
    float res[4];
    res[0] = acc0.x * dinv + b4.x;
    res[1] = acc0.y * dinv + b4.y;
    res[2] = acc0.z * dinv + b4.z;
    res[3] = acc0.w * dinv + b4.w;

    if (MODE == 0) {
        float s = 0.f, s2 = 0.f;
        #pragma unroll
        for (int q = 0; q < 4; q++) { s += res[q]; s2 += res[q] * res[q]; }
        #pragma unroll
        for (int o = 16; o > 0; o >>= 1) {
            s  += __shfl_xor_sync(0xffffffffu, s, o);
            s2 += __shfl_xor_sync(0xffffffffu, s2, o);
        }
        if (WPN == 2) {
            if (lane == 0) { ssum[warp] = s; ssum2[warp] = s2; }
            __syncthreads();
            s += ssum[warp ^ 1];
            s2 += ssum2[warp ^ 1];
        }
        float mu = s / F;
        float var = s2 / F - mu * mu;
        float rstd = rsqrtf(var + 1e-5f);
        float4 g4 = *(const float4*)(lng + col);
        float4 bb4 = *(const float4*)(lnb + col);
        float4 o4;
        o4.x = (res[0] - mu) * rstd * g4.x + bb4.x;
        o4.y = (res[1] - mu) * rstd * g4.y + bb4.y;
        o4.z = (res[2] - mu) * rstd * g4.z + bb4.z;
        o4.w = (res[3] - mu) * rstd * g4.w + bb4.w;
        o4.x = o4.x > 0.f ? o4.x : 0.f;
        o4.y = o4.y > 0.f ? o4.y : 0.f;
        o4.z = o4.z > 0.f ? o4.z : 0.f;
        o4.w = o4.w > 0.f ? o4.w : 0.f;
        *(float4*)(out + (size_t)node * F + col) = o4;
    } else {
        float4 o4 = make_float4(res[0], res[1], res[2], res[3]);
        *(float4*)(out + (size_t)node * F + col) = o4;
        *(float4*)(out2 + (size_t)node * 256 + col) = o4;
    }
}

// ---------------- host ----------------
extern "C" void kernel_launch(void* const* d_in, const int* in_sizes, int n_in,
                              void* d_out, int out_size) {
    const float* x    = (const float*)d_in[0];
    const int*   ei   = (const int*)d_in[1];
    const float* pos  = (const float*)d_in[2];
    const float* W1   = (const float*)d_in[3];
    const float* a_s1 = (const float*)d_in[4];
    const float* a_d1 = (const float*)d_in[5];
    const float* bg1  = (const float*)d_in[6];
    const float* ln1g = (const float*)d_in[7];
    const float* ln1b = (const float*)d_in[8];
    const float* W2   = (const float*)d_in[9];
    const float* a_s2 = (const float*)d_in[10];
    const float* a_d2 = (const float*)d_in[11];
    const float* bg2  = (const float*)d_in[12];
    const float* ln2g = (const float*)d_in[13];
    const float* ln2b = (const float*)d_in[14];
    const float* W3   = (const float*)d_in[15];
    const float* a_s3 = (const float*)d_in[16];
    const float* a_d3 = (const float*)d_in[17];
    const float* bg3  = (const float*)d_in[18];
    const float* pw1  = (const float*)d_in[19];
    const float* pb1  = (const float*)d_in[20];
    const float* bn1g = (const float*)d_in[21];
    const float* bn1b = (const float*)d_in[22];
    const float* pw2  = (const float*)d_in[23];
    const float* pb2  = (const float*)d_in[24];
    const float* bn2g = (const float*)d_in[25];
    const float* bn2b = (const float*)d_in[26];
    const float* pw3  = (const float*)d_in[27];
    const float* pb3  = (const float*)d_in[28];
    const float* fw   = (const float*)d_in[29];
    const float* fb   = (const float*)d_in[30];

    float* out       = (float*)d_out;
    float* out_final = out;                    // [N,128]
    float* out_x3    = out + (size_t)NN * 128; // [N,128]
    float* out_pos   = out + (size_t)NN * 256; // [N,128]

    float *pH, *pX1, *pX2, *pComb, *pP1, *pP2, *pES, *pED;
    int *pCnt;
    cudaGetSymbolAddress((void**)&pH, g_h);
    cudaGetSymbolAddress((void**)&pX1, g_x1);
    cudaGetSymbolAddress((void**)&pX2, g_x2);
    cudaGetSymbolAddress((void**)&pComb, g_comb);
    cudaGetSymbolAddress((void**)&pP1, g_p1);
    cudaGetSymbolAddress((void**)&pP2, g_p2);
    cudaGetSymbolAddress((void**)&pES, g_es);
    cudaGetSymbolAddress((void**)&pED, g_ed);
    cudaGetSymbolAddress((void**)&pCnt, g_cnt);

    cudaMemsetAsync(pCnt, 0, NN * sizeof(int));

    const int GY = NN / 64;   // 625, exact

    // (1) merged CSR build + pointnet layer 1
    prep_kernel<<<EB + PB, 256>>>(ei, pos, pw1, pb1, bn1g, bn1b, pP1);

    // (2) dual gemm: GAT layer-1 (m=256,k=64, fused scores) + pointnet gemm2
    {
        GemmJob j0 = { x, W1, nullptr, nullptr, nullptr, pH, 256, nullptr, 0,
                       NN, 256, 64, a_s1, a_d1, pES, pED, 4, 64, 4 };
        GemmJob j1 = { pP1, pw2, pb2, bn2g, bn2b, pP2, 128, nullptr, 0,
                       NN, 128, 64, nullptr, nullptr, nullptr, nullptr, 0, 0, 2 };
        gemm_dual<<<dim3(4, GY, 2), 128>>>(j0, j1);
    }
    // (3) agg layer 1
    gat_agg<4, 256, 0, 2, 0><<<NN / 4, 256>>>(bg1, ln1g, ln1b, pX1, nullptr);

    // (4) dual gemm: GAT layer-2 (m=128,k=256) + pointnet gemm3 (m=128,k=128)
    {
        GemmJob j0 = { pX1, W2, nullptr, nullptr, nullptr, pH, 128, nullptr, 0,
                       NN, 128, 256, a_s2, a_d2, pES, pED, 2, 64, 2 };
        GemmJob j1 = { pP2, pw3, pb3, nullptr, nullptr, out_pos, 128, pComb + 128, 256,
                       NN, 128, 128, nullptr, nullptr, nullptr, nullptr, 0, 0, 2 };
        gemm_dual<<<dim3(2, GY, 2), 128>>>(j0, j1);
    }
    // (5) agg layer 2
    gat_agg<2, 128, 0, 1, 0><<<NN / 8, 256>>>(bg2, ln2g, ln2b, pX2, nullptr);

    // (6) GAT layer-3 gemm (m=128,k=128): split partial scores
    {
        GemmJob j0 = { pX2, W3, nullptr, nullptr, nullptr, pH, 128, nullptr, 0,
                       NN, 128, 128, a_s3, a_d3, pES, pED, 1, 128, 2 };
        gemm_one<<<dim3(2, GY), 128>>>(j0);
    }
    // (7) agg layer 3 -> x3 output + comb[:, :128]
    gat_agg<1, 128, 1, 1, 1><<<NN / 8, 256>>>(bg3, nullptr, nullptr, out_x3, pComb);

    // (8) fusion gemm
    {
        GemmJob j0 = { pComb, fw, fb, nullptr, nullptr, out_final, 128, nullptr, 0,
                       NN, 128, 256, nullptr, nullptr, nullptr, nullptr, 0, 0, 2 };
        gemm_one<<<dim3(2, GY), 128>>>(j0);
    }
}